// round 8
// baseline (speedup 1.0000x reference)
#include <cuda_runtime.h>
#include <math.h>
#include <stdint.h>

#define BB 64
#define SS 1024
#define EE 128
#define PC 640              // gK(128) gV(128) logitK(128) P1(128) P2(128)
#define INV_SQRT_E  0.08838834764831845f
#define FULLM 0xffffffffu

// libdevice precise exp/log (bit-identical to XLA's lowering; immune to fast-math)
extern "C" __device__ float __nv_expf(float);
extern "C" __device__ float __nv_logf(float);

// XLA f32 tanh: rational polynomial with |x|<0.0004 -> x shortcut.
// Emulated with explicit non-contracted mul/add and IEEE division.
__device__ __forceinline__ float xla_tanh(float x) {
    float xc = fminf(fmaxf(x, -7.99881172180175781f), 7.99881172180175781f);
    float x2 = __fmul_rn(xc, xc);
    float p = __fadd_rn(__fmul_rn(x2, -2.76076847742355e-16f), 2.00018790482477e-13f);
    p = __fadd_rn(__fmul_rn(x2, p), -8.60467152213735e-11f);
    p = __fadd_rn(__fmul_rn(x2, p), 5.12229709037114e-08f);
    p = __fadd_rn(__fmul_rn(x2, p), 1.48572235717979e-05f);
    p = __fadd_rn(__fmul_rn(x2, p), 6.37261928875436e-04f);
    p = __fadd_rn(__fmul_rn(x2, p), 4.89352455891786e-03f);
    p = __fmul_rn(xc, p);
    float q = __fadd_rn(__fmul_rn(x2, 1.19825839466702e-06f), 1.18534705686654e-04f);
    q = __fadd_rn(__fmul_rn(x2, q), 2.26843463243900e-03f);
    q = __fadd_rn(__fmul_rn(x2, q), 4.89352518554385e-03f);
    float r = __fdiv_rn(p, q);
    return (fabsf(x) < 0.0004f) ? x : r;
}

// -------- static device scratch --------
__device__ float g_Wall[128 * PC];
__device__ float g_proj[(size_t)BB * SS * PC];   // 168 MB

// ============================================================================
// Kernel 0: combined weights [gK|gV|logitK|P1|P2]
// ============================================================================
__global__ void prep_kernel(const float* __restrict__ W_node,
                            const float* __restrict__ W_upd) {
    int tid = blockIdx.x * blockDim.x + threadIdx.x;
    int stride = blockDim.x * gridDim.x;
    for (int idx = tid; idx < 128 * 384; idx += stride) {
        int k = idx / 384, c = idx % 384;
        g_Wall[k * PC + c] = W_node[k * 384 + c];
    }
    for (int idx = tid; idx < 256 * 128; idx += stride) {
        int k2 = idx >> 7, j = idx & 127;
        float v = W_upd[idx];
        if (k2 < 128) g_Wall[k2 * PC + 384 + j] = v;
        else          g_Wall[(k2 - 128) * PC + 512 + j] = v;
    }
}

// ============================================================================
// Kernel 1: fp32 GEMM (sequential-k FFMA, one accumulator — cuBLAS-like)
// ============================================================================
__global__ __launch_bounds__(256) void gemm_kernel(const float* __restrict__ A) {
    extern __shared__ float sh[];
    float* As = sh;              // [128][65]
    float* Bs = sh + 128 * 65;   // [128][128]
    int row0 = blockIdx.x * 64, col0 = blockIdx.y * 128, tid = threadIdx.x;

    for (int idx = tid; idx < 64 * 128; idx += 256) {
        int r = idx >> 7, k = idx & 127;
        As[k * 65 + r] = A[(size_t)(row0 + r) * 128 + k];
    }
    for (int idx = tid; idx < 128 * 128; idx += 256) {
        int k = idx >> 7, c = idx & 127;
        Bs[k * 128 + c] = g_Wall[k * PC + col0 + c];
    }
    __syncthreads();

    int tx = tid & 15, ty = tid >> 4;
    int r0 = ty * 4, c0 = tx * 8;
    float acc[4][8];
#pragma unroll
    for (int i = 0; i < 4; i++)
#pragma unroll
        for (int j = 0; j < 8; j++) acc[i][j] = 0.f;
#pragma unroll 8
    for (int k = 0; k < 128; k++) {
        float a0 = As[k*65+r0], a1 = As[k*65+r0+1], a2 = As[k*65+r0+2], a3 = As[k*65+r0+3];
        float4 b0 = *(float4*)&Bs[k*128+c0];
        float4 b1 = *(float4*)&Bs[k*128+c0+4];
        float bb[8] = {b0.x,b0.y,b0.z,b0.w,b1.x,b1.y,b1.z,b1.w};
#pragma unroll
        for (int j = 0; j < 8; j++) {
            acc[0][j] += a0*bb[j]; acc[1][j] += a1*bb[j];
            acc[2][j] += a2*bb[j]; acc[3][j] += a3*bb[j];
        }
    }
#pragma unroll
    for (int i = 0; i < 4; i++) {
        size_t o = (size_t)(row0+r0+i)*PC + col0 + c0;
        *(float4*)&g_proj[o]   = make_float4(acc[i][0],acc[i][1],acc[i][2],acc[i][3]);
        *(float4*)&g_proj[o+4] = make_float4(acc[i][4],acc[i][5],acc[i][6],acc[i][7]);
    }
}

// ============================================================================
// Kernel 2: persistent decode, 1 CTA/batch, 1024 threads.
// City selection emulates the reference exactly:
//   logp_i = fl(fl(x_i - m) - L),  L = __nv_logf(S),
//   S = XLA-style row reduction (512 thr x vec2 + warp shfl trees),
//   city = argmax(logp) with first-index tie-break.
// ============================================================================
struct DS {
    float wout[128 * 128];
    float compat[8 * 1032];
    float part[32 * 128];
    float logits[1024];
    float evals[1024];       // exp values, then logp
    float q[128], hhat[128], phq[128], heads[128], glim[128];
    float redv[32];
    float redf[16];          // [0:8] head max, [8:16] 1/sum
    float fvars[4];          // [0] m (max logit), [1] L
    int   redi[32];
    int   ivars[4];          // [0] first, [1] last, [2] city
    unsigned char mask[1024];
};

__global__ __launch_bounds__(1024, 1) void decode_kernel(
    const float* __restrict__ enc,
    const float* __restrict__ W_ctx,
    const float* __restrict__ W_upd,
    const float* __restrict__ W_out,
    const float* __restrict__ W_ph,
    float* __restrict__ out)
{
    extern __shared__ char smem_raw[];
    DS& sm = *reinterpret_cast<DS*>(smem_raw);

    const int b = blockIdx.x, tid = threadIdx.x;
    const int lane = tid & 31, warp = tid >> 5;
    const float NEGINF = -INFINITY;

    const float* __restrict__ projb = g_proj + (size_t)b * SS * PC;
    const float* __restrict__ encb  = enc + (size_t)b * SS * EE;

    // ---- init ----
    for (int idx = tid; idx < 128 * 128; idx += 1024)
        sm.wout[idx] = W_out[idx];
    sm.mask[tid] = 0;
    {
        int e = tid & 127, g = tid >> 7;
        float acc = 0.f;
        for (int i = 0; i < 128; i++)
            acc += encb[(size_t)(g * 128 + i) * EE + e];
        sm.part[g * 128 + e] = acc;
    }
    __syncthreads();
    if (tid < 128) {
        float m = 0.f;
#pragma unroll
        for (int g = 0; g < 8; g++) m += sm.part[g * 128 + tid];
        sm.q[tid] = m * (1.0f / 1024.0f);
    }
    __syncthreads();
    if (tid < 128) {
        float h = 0.f;
#pragma unroll 8
        for (int k = 0; k < 128; k++) h += sm.q[k] * W_ctx[k * 128 + tid];
        sm.hhat[tid] = h;
    } else if (tid < 256) {
        int e = tid - 128;
        float p = 0.f;
#pragma unroll 8
        for (int k = 0; k < 256; k++) p += W_ph[k] * W_upd[k * 128 + e];
        sm.phq[e] = p;
    }
    if (tid == 0) { sm.ivars[0] = 0; sm.ivars[1] = 0; }
    __syncthreads();

    double logp_sum = 0.0;

    for (int t = 0; t < SS; t++) {
        // ---- q ----
        if (tid < 128) {
            float qv = sm.hhat[tid];
            if (t == 0) qv += sm.phq[tid];
            else {
                int f = sm.ivars[0], l = sm.ivars[1];
                qv += projb[(size_t)f * PC + 384 + tid] + projb[(size_t)l * PC + 512 + tid];
            }
            sm.q[tid] = qv;
        }
        __syncthreads();

        // ---- compat per head ----
        {
            float4 qv = *(float4*)&sm.q[lane * 4];
            int h = lane >> 2;
#pragma unroll 4
            for (int i = 0; i < 32; i++) {
                int s = warp * 32 + i;
                float4 g = *(const float4*)(projb + (size_t)s * PC + lane * 4);
                float v = g.x*qv.x + g.y*qv.y + g.z*qv.z + g.w*qv.w;
                v += __shfl_xor_sync(FULLM, v, 1);
                v += __shfl_xor_sync(FULLM, v, 2);
                float cv = sm.mask[s] ? NEGINF : v * 0.25f;
                if ((lane & 3) == 0) sm.compat[h * 1032 + s] = cv;
            }
        }
        __syncthreads();

        // ---- softmax-attn: per-head max, exp, sum ----
        {
            int gh = tid >> 7, j = tid & 127;
            float mx = NEGINF;
#pragma unroll
            for (int ii = 0; ii < 8; ii++)
                mx = fmaxf(mx, sm.compat[gh * 1032 + j + ii * 128]);
#pragma unroll
            for (int off = 16; off; off >>= 1)
                mx = fmaxf(mx, __shfl_xor_sync(FULLM, mx, off));
            if (lane == 0) sm.redv[warp] = mx;
        }
        __syncthreads();
        if (tid < 8) {
            float m = fmaxf(fmaxf(sm.redv[tid*4], sm.redv[tid*4+1]),
                            fmaxf(sm.redv[tid*4+2], sm.redv[tid*4+3]));
            sm.redf[tid] = m;
        }
        __syncthreads();
        {
            int gh = tid >> 7, j = tid & 127;
            float hm = sm.redf[gh];
            float se = 0.f;
#pragma unroll
            for (int ii = 0; ii < 8; ii++) {
                int idx = gh * 1032 + j + ii * 128;
                float ev = __nv_expf(sm.compat[idx] - hm);
                sm.compat[idx] = ev;
                se += ev;
            }
#pragma unroll
            for (int off = 16; off; off >>= 1)
                se += __shfl_xor_sync(FULLM, se, off);
            if (lane == 0) sm.redv[warp] = se;
        }
        __syncthreads();
        if (tid < 8) {
            float s = sm.redv[tid*4] + sm.redv[tid*4+1] + sm.redv[tid*4+2] + sm.redv[tid*4+3];
            sm.redf[8 + tid] = 1.0f / s;
        }
        __syncthreads();

        // ---- heads ----
        {
            int h = lane >> 2;
            float invs = sm.redf[8 + h];
            float4 acc = make_float4(0.f, 0.f, 0.f, 0.f);
#pragma unroll 4
            for (int i = 0; i < 32; i++) {
                int s = warp * 32 + i;
                float a = sm.compat[h * 1032 + s] * invs;
                float4 g = *(const float4*)(projb + (size_t)s * PC + 128 + lane * 4);
                acc.x += a*g.x; acc.y += a*g.y; acc.z += a*g.z; acc.w += a*g.w;
            }
            ((float4*)&sm.part[warp * 128])[lane] = acc;
        }
        __syncthreads();
        {
            int e = tid & 127, g = tid >> 7;
            float p = sm.part[(g*4+0)*128+e] + sm.part[(g*4+1)*128+e]
                    + sm.part[(g*4+2)*128+e] + sm.part[(g*4+3)*128+e];
            sm.part[(g*4)*128+e] = p;
        }
        __syncthreads();
        if (tid < 128) {
            float hsum = 0.f;
#pragma unroll
            for (int g = 0; g < 8; g++) hsum += sm.part[(g*4)*128+tid];
            sm.heads[tid] = hsum;
        }
        __syncthreads();

        // ---- glimpse = heads @ W_out ----
        if (tid < 128) {
            float gl = 0.f;
#pragma unroll 8
            for (int f = 0; f < 128; f++) gl += sm.heads[f] * sm.wout[f*128+tid];
            sm.glim[tid] = gl;
        }
        __syncthreads();

        // ---- logits: 10 * xla_tanh(dot * inv_sqrt_e), masked ----
        {
            float4 hv = *(float4*)&sm.glim[lane * 4];
#pragma unroll 4
            for (int i = 0; i < 32; i++) {
                int s = warp * 32 + i;
                float4 g = *(const float4*)(projb + (size_t)s * PC + 256 + lane * 4);
                float v = g.x*hv.x + g.y*hv.y + g.z*hv.z + g.w*hv.w;
#pragma unroll
                for (int off = 16; off; off >>= 1)
                    v += __shfl_xor_sync(FULLM, v, off);
                if (lane == 0)
                    sm.logits[s] = sm.mask[s] ? NEGINF
                        : __fmul_rn(10.0f, xla_tanh(__fmul_rn(v, INV_SQRT_E)));
            }
        }
        __syncthreads();

        // ---- m = max(logits) (exact, order-free) ----
        {
            float v = sm.logits[tid];
#pragma unroll
            for (int off = 16; off; off >>= 1)
                v = fmaxf(v, __shfl_xor_sync(FULLM, v, off));
            if (lane == 0) sm.redv[warp] = v;
        }
        __syncthreads();
        if (warp == 0) {
            float v = sm.redv[lane];
#pragma unroll
            for (int off = 16; off; off >>= 1)
                v = fmaxf(v, __shfl_xor_sync(FULLM, v, off));
            if (lane == 0) sm.fvars[0] = v;
        }
        __syncthreads();

        // ---- e_s = exp(x_s - m) ----
        {
            float m = sm.fvars[0];
            sm.evals[tid] = __nv_expf(__fsub_rn(sm.logits[tid], m));  // -inf -> 0
        }
        __syncthreads();

        // ---- S: XLA row reduction (512 thr x vec2 -> warp trees -> warp0 tree) ----
        if (tid < 512) {
            float v = __fadd_rn(sm.evals[2*tid], sm.evals[2*tid + 1]);
            v = __fadd_rn(v, __shfl_down_sync(FULLM, v, 16));
            v = __fadd_rn(v, __shfl_down_sync(FULLM, v, 8));
            v = __fadd_rn(v, __shfl_down_sync(FULLM, v, 4));
            v = __fadd_rn(v, __shfl_down_sync(FULLM, v, 2));
            v = __fadd_rn(v, __shfl_down_sync(FULLM, v, 1));
            if (lane == 0) sm.redv[warp] = v;   // warps 0..15
        }
        __syncthreads();
        if (warp == 0) {
            float v = (lane < 16) ? sm.redv[lane] : 0.0f;
            v = __fadd_rn(v, __shfl_down_sync(FULLM, v, 16));
            v = __fadd_rn(v, __shfl_down_sync(FULLM, v, 8));
            v = __fadd_rn(v, __shfl_down_sync(FULLM, v, 4));
            v = __fadd_rn(v, __shfl_down_sync(FULLM, v, 2));
            v = __fadd_rn(v, __shfl_down_sync(FULLM, v, 1));
            if (lane == 0) sm.fvars[1] = __nv_logf(v);
        }
        __syncthreads();

        // ---- logp_i = (x_i - m) - L, quantized; argmax first-index ----
        {
            float m = sm.fvars[0], L = sm.fvars[1];
            float lp = __fsub_rn(__fsub_rn(sm.logits[tid], m), L);
            sm.evals[tid] = lp;   // keep for logp_sum
            float v = lp;
            int idx = tid;
#pragma unroll
            for (int off = 16; off; off >>= 1) {
                float ov = __shfl_xor_sync(FULLM, v, off);
                int   oi = __shfl_xor_sync(FULLM, idx, off);
                if (ov > v || (ov == v && oi < idx)) { v = ov; idx = oi; }
            }
            if (lane == 0) { sm.redv[warp] = v; sm.redi[warp] = idx; }
        }
        __syncthreads();
        if (warp == 0) {
            float v = sm.redv[lane];
            int idx = sm.redi[lane];
#pragma unroll
            for (int off = 16; off; off >>= 1) {
                float ov = __shfl_xor_sync(FULLM, v, off);
                int   oi = __shfl_xor_sync(FULLM, idx, off);
                if (ov > v || (ov == v && oi < idx)) { v = ov; idx = oi; }
            }
            if (lane == 0) sm.ivars[2] = idx;
        }
        __syncthreads();

        // ---- state update + output ----
        if (tid == 0) {
            int city = sm.ivars[2];
            logp_sum += (double)sm.evals[city];
            sm.mask[city] = 1;
            sm.ivars[1] = city;
            if (t == 0) sm.ivars[0] = city;
            out[BB + b * SS + t] = (float)city;
        }
        __syncthreads();
    }

    if (tid == 0) out[b] = (float)logp_sum;
}

// ============================================================================
extern "C" void kernel_launch(void* const* d_in, const int* in_sizes, int n_in,
                              void* d_out, int out_size) {
    const float* enc    = (const float*)d_in[0];
    const float* W_ctx  = (const float*)d_in[1];
    const float* W_upd  = (const float*)d_in[2];
    const float* W_node = (const float*)d_in[3];
    const float* W_out  = (const float*)d_in[4];
    const float* W_ph   = (const float*)d_in[5];
    float* out = (float*)d_out;

    static const int GEMM_SMEM = (128 * 65 + 128 * 128) * sizeof(float);
    static const int DEC_SMEM  = (int)sizeof(DS);
    cudaFuncSetAttribute(gemm_kernel,  cudaFuncAttributeMaxDynamicSharedMemorySize, GEMM_SMEM);
    cudaFuncSetAttribute(decode_kernel, cudaFuncAttributeMaxDynamicSharedMemorySize, DEC_SMEM);

    prep_kernel<<<16, 1024>>>(W_node, W_upd);
    gemm_kernel<<<dim3((BB * SS) / 64, PC / 128), 256, GEMM_SMEM>>>(enc);
    decode_kernel<<<BB, 1024, DEC_SMEM>>>(enc, W_ctx, W_upd, W_out, W_ph, out);
}

// round 9
// speedup vs baseline: 1.4294x; 1.4294x over previous
#include <cuda_runtime.h>
#include <math.h>
#include <stdint.h>

#define BB 64
#define SS 1024
#define EE 128
#define PC 640              // gK(128) gV(128) logitK(128) P1(128) P2(128)
#define INV_SQRT_E  0.08838834764831845f
#define FULLM 0xffffffffu

extern "C" __device__ float __nv_expf(float);
extern "C" __device__ float __nv_logf(float);

// XLA f32 tanh (frozen numerics — do not touch)
__device__ __forceinline__ float xla_tanh(float x) {
    float xc = fminf(fmaxf(x, -7.99881172180175781f), 7.99881172180175781f);
    float x2 = __fmul_rn(xc, xc);
    float p = __fadd_rn(__fmul_rn(x2, -2.76076847742355e-16f), 2.00018790482477e-13f);
    p = __fadd_rn(__fmul_rn(x2, p), -8.60467152213735e-11f);
    p = __fadd_rn(__fmul_rn(x2, p), 5.12229709037114e-08f);
    p = __fadd_rn(__fmul_rn(x2, p), 1.48572235717979e-05f);
    p = __fadd_rn(__fmul_rn(x2, p), 6.37261928875436e-04f);
    p = __fadd_rn(__fmul_rn(x2, p), 4.89352455891786e-03f);
    p = __fmul_rn(xc, p);
    float q = __fadd_rn(__fmul_rn(x2, 1.19825839466702e-06f), 1.18534705686654e-04f);
    q = __fadd_rn(__fmul_rn(x2, q), 2.26843463243900e-03f);
    q = __fadd_rn(__fmul_rn(x2, q), 4.89352518554385e-03f);
    float r = __fdiv_rn(p, q);
    return (fabsf(x) < 0.0004f) ? x : r;
}

__device__ float g_Wall[128 * PC];
__device__ float g_proj[(size_t)BB * SS * PC];   // 168 MB

// ============================================================================
__global__ void prep_kernel(const float* __restrict__ W_node,
                            const float* __restrict__ W_upd) {
    int tid = blockIdx.x * blockDim.x + threadIdx.x;
    int stride = blockDim.x * gridDim.x;
    for (int idx = tid; idx < 128 * 384; idx += stride) {
        int k = idx / 384, c = idx % 384;
        g_Wall[k * PC + c] = W_node[k * 384 + c];
    }
    for (int idx = tid; idx < 256 * 128; idx += stride) {
        int k2 = idx >> 7, j = idx & 127;
        float v = W_upd[idx];
        if (k2 < 128) g_Wall[k2 * PC + 384 + j] = v;
        else          g_Wall[(k2 - 128) * PC + 512 + j] = v;
    }
}

// ============================================================================
__global__ __launch_bounds__(256) void gemm_kernel(const float* __restrict__ A) {
    extern __shared__ float sh[];
    float* As = sh;              // [128][65]
    float* Bs = sh + 128 * 65;   // [128][128]
    int row0 = blockIdx.x * 64, col0 = blockIdx.y * 128, tid = threadIdx.x;

    for (int idx = tid; idx < 64 * 128; idx += 256) {
        int r = idx >> 7, k = idx & 127;
        As[k * 65 + r] = A[(size_t)(row0 + r) * 128 + k];
    }
    for (int idx = tid; idx < 128 * 128; idx += 256) {
        int k = idx >> 7, c = idx & 127;
        Bs[k * 128 + c] = g_Wall[k * PC + col0 + c];
    }
    __syncthreads();

    int tx = tid & 15, ty = tid >> 4;
    int r0 = ty * 4, c0 = tx * 8;
    float acc[4][8];
#pragma unroll
    for (int i = 0; i < 4; i++)
#pragma unroll
        for (int j = 0; j < 8; j++) acc[i][j] = 0.f;
#pragma unroll 8
    for (int k = 0; k < 128; k++) {
        float a0 = As[k*65+r0], a1 = As[k*65+r0+1], a2 = As[k*65+r0+2], a3 = As[k*65+r0+3];
        float4 b0 = *(float4*)&Bs[k*128+c0];
        float4 b1 = *(float4*)&Bs[k*128+c0+4];
        float bb[8] = {b0.x,b0.y,b0.z,b0.w,b1.x,b1.y,b1.z,b1.w};
#pragma unroll
        for (int j = 0; j < 8; j++) {
            acc[0][j] += a0*bb[j]; acc[1][j] += a1*bb[j];
            acc[2][j] += a2*bb[j]; acc[3][j] += a3*bb[j];
        }
    }
#pragma unroll
    for (int i = 0; i < 4; i++) {
        size_t o = (size_t)(row0+r0+i)*PC + col0 + c0;
        *(float4*)&g_proj[o]   = make_float4(acc[i][0],acc[i][1],acc[i][2],acc[i][3]);
        *(float4*)&g_proj[o+4] = make_float4(acc[i][4],acc[i][5],acc[i][6],acc[i][7]);
    }
}

// ============================================================================
// Decode: 10 barriers/step (serial replays of identical reduction orders),
// mask-skip on all three streaming loops (bit-exact), unroll 8.
// ============================================================================
struct DS {
    float wout[128 * 128];
    float compat[8 * 1032];
    float part[32 * 128];
    float logits[1024];
    float q[128], hhat[128], phq[128], heads[128], glim[128];
    float redv[32];    // P2: per-warp head maxes | P7: per-warp logit maxes
    float redv2[32];   // P3: per-warp exp sums  | P8: 16 pair-tree partials
    float redv3[32];   // P9: per-warp argmax value
    int   redi[32];    // P9: per-warp argmax index
    unsigned char mask[1024];
};

__global__ __launch_bounds__(1024, 1) void decode_kernel(
    const float* __restrict__ enc,
    const float* __restrict__ W_ctx,
    const float* __restrict__ W_upd,
    const float* __restrict__ W_out,
    const float* __restrict__ W_ph,
    float* __restrict__ out)
{
    extern __shared__ char smem_raw[];
    DS& sm = *reinterpret_cast<DS*>(smem_raw);

    const int b = blockIdx.x, tid = threadIdx.x;
    const int lane = tid & 31, warp = tid >> 5;
    const float NEGINF = -INFINITY;

    const float* __restrict__ projb = g_proj + (size_t)b * SS * PC;
    const float* __restrict__ encb  = enc + (size_t)b * SS * EE;

    // ---- init (numerics identical to R8) ----
    for (int idx = tid; idx < 128 * 128; idx += 1024)
        sm.wout[idx] = W_out[idx];
    sm.mask[tid] = 0;
    {
        int e = tid & 127, g = tid >> 7;
        float acc = 0.f;
        for (int i = 0; i < 128; i++)
            acc += encb[(size_t)(g * 128 + i) * EE + e];
        sm.part[g * 128 + e] = acc;
    }
    __syncthreads();
    if (tid < 128) {
        float m = 0.f;
#pragma unroll
        for (int g = 0; g < 8; g++) m += sm.part[g * 128 + tid];
        sm.q[tid] = m * (1.0f / 1024.0f);
    }
    __syncthreads();
    if (tid < 128) {
        float h = 0.f;
#pragma unroll 8
        for (int k = 0; k < 128; k++) h += sm.q[k] * W_ctx[k * 128 + tid];
        sm.hhat[tid] = h;
    } else if (tid < 256) {
        int e = tid - 128;
        float p = 0.f;
#pragma unroll 8
        for (int k = 0; k < 256; k++) p += W_ph[k] * W_upd[k * 128 + e];
        sm.phq[e] = p;
    }
    __syncthreads();
    if (tid < 128) {
        float qv = sm.hhat[tid];
        qv += sm.phq[tid];           // t=0 placeholder q
        sm.q[tid] = qv;
    }
    __syncthreads();

    int first_r = 0;
    double logp_sum = 0.0;   // used by tid 0

    for (int t = 0; t < SS; t++) {
        // ---- P1: compat (reads q, gK; mask-skip) ----
        {
            float4 qv = *(float4*)&sm.q[lane * 4];
            int h = lane >> 2;
#pragma unroll 8
            for (int i = 0; i < 32; i++) {
                int s = warp * 32 + i;
                if (sm.mask[s]) {
                    if ((lane & 3) == 0) sm.compat[h * 1032 + s] = NEGINF;
                } else {
                    float4 g = *(const float4*)(projb + (size_t)s * PC + lane * 4);
                    float v = g.x*qv.x + g.y*qv.y + g.z*qv.z + g.w*qv.w;
                    v += __shfl_xor_sync(FULLM, v, 1);
                    v += __shfl_xor_sync(FULLM, v, 2);
                    if ((lane & 3) == 0) sm.compat[h * 1032 + s] = v * 0.25f;
                }
            }
        }
        __syncthreads();

        // ---- P2: per-warp head max -> redv[warp] ----
        {
            int gh = tid >> 7, j = tid & 127;
            float mx = NEGINF;
#pragma unroll
            for (int ii = 0; ii < 8; ii++)
                mx = fmaxf(mx, sm.compat[gh * 1032 + j + ii * 128]);
#pragma unroll
            for (int off = 16; off; off >>= 1)
                mx = fmaxf(mx, __shfl_xor_sync(FULLM, mx, off));
            if (lane == 0) sm.redv[warp] = mx;
        }
        __syncthreads();

        // ---- P3: hm replay + exp + per-warp sum -> redv2[warp] ----
        {
            int gh = tid >> 7, j = tid & 127;
            float hm = fmaxf(fmaxf(sm.redv[gh*4], sm.redv[gh*4+1]),
                             fmaxf(sm.redv[gh*4+2], sm.redv[gh*4+3]));
            float se = 0.f;
#pragma unroll
            for (int ii = 0; ii < 8; ii++) {
                int idx = gh * 1032 + j + ii * 128;
                float ev = __nv_expf(sm.compat[idx] - hm);
                sm.compat[idx] = ev;
                se += ev;
            }
#pragma unroll
            for (int off = 16; off; off >>= 1)
                se += __shfl_xor_sync(FULLM, se, off);
            if (lane == 0) sm.redv2[warp] = se;
        }
        __syncthreads();

        // ---- P4: invs replay + heads partials (reads gV; mask-skip) ----
        {
            int h = lane >> 2;
            float s4 = sm.redv2[h*4] + sm.redv2[h*4+1] + sm.redv2[h*4+2] + sm.redv2[h*4+3];
            float invs = 1.0f / s4;
            float4 acc = make_float4(0.f, 0.f, 0.f, 0.f);
#pragma unroll 8
            for (int i = 0; i < 32; i++) {
                int s = warp * 32 + i;
                if (!sm.mask[s]) {
                    float a = sm.compat[h * 1032 + s] * invs;
                    float4 g = *(const float4*)(projb + (size_t)s * PC + 128 + lane * 4);
                    acc.x += a*g.x; acc.y += a*g.y; acc.z += a*g.z; acc.w += a*g.w;
                }
            }
            ((float4*)&sm.part[warp * 128])[lane] = acc;
        }
        __syncthreads();

        // ---- P5: heads reduce (replay of original 2-stage order) ----
        if (tid < 128) {
            float hsum = 0.f;
#pragma unroll
            for (int g = 0; g < 8; g++) {
                float pg = sm.part[(g*4+0)*128+tid] + sm.part[(g*4+1)*128+tid]
                         + sm.part[(g*4+2)*128+tid] + sm.part[(g*4+3)*128+tid];
                hsum += pg;
            }
            sm.heads[tid] = hsum;
        }
        __syncthreads();

        // ---- P6: glimpse ----
        if (tid < 128) {
            float gl = 0.f;
#pragma unroll 8
            for (int f = 0; f < 128; f++) gl += sm.heads[f] * sm.wout[f*128+tid];
            sm.glim[tid] = gl;
        }
        __syncthreads();

        // ---- P7: logits (reads logitK; mask-skip) + lane0-tracked warp max ----
        {
            float4 hv = *(float4*)&sm.glim[lane * 4];
            float wmax = NEGINF;
#pragma unroll 8
            for (int i = 0; i < 32; i++) {
                int s = warp * 32 + i;
                if (sm.mask[s]) {
                    if (lane == 0) sm.logits[s] = NEGINF;
                } else {
                    float4 g = *(const float4*)(projb + (size_t)s * PC + 256 + lane * 4);
                    float v = g.x*hv.x + g.y*hv.y + g.z*hv.z + g.w*hv.w;
#pragma unroll
                    for (int off = 16; off; off >>= 1)
                        v += __shfl_xor_sync(FULLM, v, off);
                    float lv = __fmul_rn(10.0f, xla_tanh(__fmul_rn(v, INV_SQRT_E)));
                    if (lane == 0) { sm.logits[s] = lv; wmax = fmaxf(wmax, lv); }
                }
            }
            if (lane == 0) sm.redv[warp] = wmax;
        }
        __syncthreads();

        // ---- P8: m replay; pair-exp + warp shfl-down tree -> redv2[w<16] ----
        float m_r;
        {
            m_r = sm.redv[0];
#pragma unroll
            for (int w2 = 1; w2 < 32; w2++) m_r = fmaxf(m_r, sm.redv[w2]);
            if (tid < 512) {
                float e0 = __nv_expf(__fsub_rn(sm.logits[2*tid],     m_r));
                float e1 = __nv_expf(__fsub_rn(sm.logits[2*tid + 1], m_r));
                float v = __fadd_rn(e0, e1);
                v = __fadd_rn(v, __shfl_down_sync(FULLM, v, 16));
                v = __fadd_rn(v, __shfl_down_sync(FULLM, v, 8));
                v = __fadd_rn(v, __shfl_down_sync(FULLM, v, 4));
                v = __fadd_rn(v, __shfl_down_sync(FULLM, v, 2));
                v = __fadd_rn(v, __shfl_down_sync(FULLM, v, 1));
                if (lane == 0) sm.redv2[warp] = v;
            }
        }
        __syncthreads();

        // ---- P9: L replay (exact tree), lp, per-warp argmax -> redv3/redi ----
        float L_r;
        {
            float a[16];
#pragma unroll
            for (int i2 = 0; i2 < 16; i2++) a[i2] = sm.redv2[i2];
#pragma unroll
            for (int off = 8; off; off >>= 1)
#pragma unroll
                for (int i2 = 0; i2 < 8; i2++)
                    if (i2 < off) a[i2] = __fadd_rn(a[i2], a[i2 + off]);
            L_r = __nv_logf(a[0]);

            float lp = __fsub_rn(__fsub_rn(sm.logits[tid], m_r), L_r);
            float v = lp;
            int idx = tid;
#pragma unroll
            for (int off = 16; off; off >>= 1) {
                float ov = __shfl_xor_sync(FULLM, v, off);
                int   oi = __shfl_xor_sync(FULLM, idx, off);
                if (ov > v || (ov == v && oi < idx)) { v = ov; idx = oi; }
            }
            if (lane == 0) { sm.redv3[warp] = v; sm.redi[warp] = idx; }
        }
        __syncthreads();

        // ---- P10: city replay; update; q for next step ----
        {
            float bv = sm.redv3[0]; int bi = sm.redi[0];
#pragma unroll
            for (int w2 = 1; w2 < 32; w2++) {
                float ov = sm.redv3[w2]; int oi = sm.redi[w2];
                if (ov > bv || (ov == bv && oi < bi)) { bv = ov; bi = oi; }
            }
            int city = bi;
            if (t == 0) first_r = city;
            if (tid == 0) {
                logp_sum += (double)__fsub_rn(__fsub_rn(sm.logits[city], m_r), L_r);
                sm.mask[city] = 1;
                out[BB + b * SS + t] = (float)city;
            }
            if (tid < 128) {
                // q = hhat + (P1[first] + P2[last])  — exact original association
                float pf = projb[(size_t)first_r * PC + 384 + tid];
                float pl = projb[(size_t)city   * PC + 512 + tid];
                sm.q[tid] = sm.hhat[tid] + (pf + pl);
            }
        }
        __syncthreads();
    }

    if (tid == 0) out[b] = (float)logp_sum;
}

// ============================================================================
extern "C" void kernel_launch(void* const* d_in, const int* in_sizes, int n_in,
                              void* d_out, int out_size) {
    const float* enc    = (const float*)d_in[0];
    const float* W_ctx  = (const float*)d_in[1];
    const float* W_upd  = (const float*)d_in[2];
    const float* W_node = (const float*)d_in[3];
    const float* W_out  = (const float*)d_in[4];
    const float* W_ph   = (const float*)d_in[5];
    float* out = (float*)d_out;

    static const int GEMM_SMEM = (128 * 65 + 128 * 128) * sizeof(float);
    static const int DEC_SMEM  = (int)sizeof(DS);
    cudaFuncSetAttribute(gemm_kernel,   cudaFuncAttributeMaxDynamicSharedMemorySize, GEMM_SMEM);
    cudaFuncSetAttribute(decode_kernel, cudaFuncAttributeMaxDynamicSharedMemorySize, DEC_SMEM);

    prep_kernel<<<16, 1024>>>(W_node, W_upd);
    gemm_kernel<<<dim3((BB * SS) / 64, PC / 128), 256, GEMM_SMEM>>>(enc);
    decode_kernel<<<BB, 1024, DEC_SMEM>>>(enc, W_ctx, W_upd, W_out, W_ph, out);
}

// round 10
// speedup vs baseline: 1.6393x; 1.1468x over previous
#include <cuda_runtime.h>
#include <math.h>
#include <stdint.h>

#define BB 64
#define SS 1024
#define EE 128
#define PC 640              // gK(128) gV(128) logitK(128) P1(128) P2(128)
#define INV_SQRT_E  0.08838834764831845f
#define FULLM 0xffffffffu

extern "C" __device__ float __nv_expf(float);
extern "C" __device__ float __nv_logf(float);

// XLA f32 tanh (frozen numerics — do not touch)
__device__ __forceinline__ float xla_tanh(float x) {
    float xc = fminf(fmaxf(x, -7.99881172180175781f), 7.99881172180175781f);
    float x2 = __fmul_rn(xc, xc);
    float p = __fadd_rn(__fmul_rn(x2, -2.76076847742355e-16f), 2.00018790482477e-13f);
    p = __fadd_rn(__fmul_rn(x2, p), -8.60467152213735e-11f);
    p = __fadd_rn(__fmul_rn(x2, p), 5.12229709037114e-08f);
    p = __fadd_rn(__fmul_rn(x2, p), 1.48572235717979e-05f);
    p = __fadd_rn(__fmul_rn(x2, p), 6.37261928875436e-04f);
    p = __fadd_rn(__fmul_rn(x2, p), 4.89352455891786e-03f);
    p = __fmul_rn(xc, p);
    float q = __fadd_rn(__fmul_rn(x2, 1.19825839466702e-06f), 1.18534705686654e-04f);
    q = __fadd_rn(__fmul_rn(x2, q), 2.26843463243900e-03f);
    q = __fadd_rn(__fmul_rn(x2, q), 4.89352518554385e-03f);
    float r = __fdiv_rn(p, q);
    return (fabsf(x) < 0.0004f) ? x : r;
}

__device__ float g_Wall[128 * PC];
__device__ float g_proj[(size_t)BB * SS * PC];   // 168 MB

// ============================================================================
__global__ void prep_kernel(const float* __restrict__ W_node,
                            const float* __restrict__ W_upd) {
    int tid = blockIdx.x * blockDim.x + threadIdx.x;
    int stride = blockDim.x * gridDim.x;
    for (int idx = tid; idx < 128 * 384; idx += stride) {
        int k = idx / 384, c = idx % 384;
        g_Wall[k * PC + c] = W_node[k * 384 + c];
    }
    for (int idx = tid; idx < 256 * 128; idx += stride) {
        int k2 = idx >> 7, j = idx & 127;
        float v = W_upd[idx];
        if (k2 < 128) g_Wall[k2 * PC + 384 + j] = v;
        else          g_Wall[(k2 - 128) * PC + 512 + j] = v;
    }
}

// ============================================================================
__global__ __launch_bounds__(256) void gemm_kernel(const float* __restrict__ A) {
    extern __shared__ float sh[];
    float* As = sh;              // [128][65]
    float* Bs = sh + 128 * 65;   // [128][128]
    int row0 = blockIdx.x * 64, col0 = blockIdx.y * 128, tid = threadIdx.x;

    for (int idx = tid; idx < 64 * 128; idx += 256) {
        int r = idx >> 7, k = idx & 127;
        As[k * 65 + r] = A[(size_t)(row0 + r) * 128 + k];
    }
    for (int idx = tid; idx < 128 * 128; idx += 256) {
        int k = idx >> 7, c = idx & 127;
        Bs[k * 128 + c] = g_Wall[k * PC + col0 + c];
    }
    __syncthreads();

    int tx = tid & 15, ty = tid >> 4;
    int r0 = ty * 4, c0 = tx * 8;
    float acc[4][8];
#pragma unroll
    for (int i = 0; i < 4; i++)
#pragma unroll
        for (int j = 0; j < 8; j++) acc[i][j] = 0.f;
#pragma unroll 8
    for (int k = 0; k < 128; k++) {
        float a0 = As[k*65+r0], a1 = As[k*65+r0+1], a2 = As[k*65+r0+2], a3 = As[k*65+r0+3];
        float4 b0 = *(float4*)&Bs[k*128+c0];
        float4 b1 = *(float4*)&Bs[k*128+c0+4];
        float bb[8] = {b0.x,b0.y,b0.z,b0.w,b1.x,b1.y,b1.z,b1.w};
#pragma unroll
        for (int j = 0; j < 8; j++) {
            acc[0][j] += a0*bb[j]; acc[1][j] += a1*bb[j];
            acc[2][j] += a2*bb[j]; acc[3][j] += a3*bb[j];
        }
    }
#pragma unroll
    for (int i = 0; i < 4; i++) {
        size_t o = (size_t)(row0+r0+i)*PC + col0 + c0;
        *(float4*)&g_proj[o]   = make_float4(acc[i][0],acc[i][1],acc[i][2],acc[i][3]);
        *(float4*)&g_proj[o+4] = make_float4(acc[i][4],acc[i][5],acc[i][6],acc[i][7]);
    }
}

// ============================================================================
// Decode: 9 barriers/step. Register bitmasks for mask tests; per-warp-per-head
// maxes folded into P1 (fmax is exactly order-free); parallel tanh in P7.
// All value-producing arithmetic orders identical to R9.
// ============================================================================
struct DS {
    float wout[128 * 128];
    float compat[8 * 1032];
    float part[32 * 128];
    float logits[1024];
    float q[128], hhat[128], phq[128], heads[128], glim[128];
    float redv8[32 * 8];  // P1: per-warp per-head maxes
    float redv[32];       // P7: per-warp logit maxes
    float redv2[32];      // P3: per-warp exp sums | P8: 16 pair-tree partials
    float redv3[32];      // P9: per-warp argmax value
    int   redi[32];       // P9: per-warp argmax index
};

__global__ __launch_bounds__(1024, 1) void decode_kernel(
    const float* __restrict__ enc,
    const float* __restrict__ W_ctx,
    const float* __restrict__ W_upd,
    const float* __restrict__ W_out,
    const float* __restrict__ W_ph,
    float* __restrict__ out)
{
    extern __shared__ char smem_raw[];
    DS& sm = *reinterpret_cast<DS*>(smem_raw);

    const int b = blockIdx.x, tid = threadIdx.x;
    const int lane = tid & 31, warp = tid >> 5;
    const float NEGINF = -INFINITY;

    const float* __restrict__ projb = g_proj + (size_t)b * SS * PC;
    const float* __restrict__ encb  = enc + (size_t)b * SS * EE;

    // ---- init (numerics identical to R9) ----
    for (int idx = tid; idx < 128 * 128; idx += 1024)
        sm.wout[idx] = W_out[idx];
    {
        int e = tid & 127, g = tid >> 7;
        float acc = 0.f;
        for (int i = 0; i < 128; i++)
            acc += encb[(size_t)(g * 128 + i) * EE + e];
        sm.part[g * 128 + e] = acc;
    }
    __syncthreads();
    if (tid < 128) {
        float m = 0.f;
#pragma unroll
        for (int g = 0; g < 8; g++) m += sm.part[g * 128 + tid];
        sm.q[tid] = m * (1.0f / 1024.0f);
    }
    __syncthreads();
    if (tid < 128) {
        float h = 0.f;
#pragma unroll 8
        for (int k = 0; k < 128; k++) h += sm.q[k] * W_ctx[k * 128 + tid];
        sm.hhat[tid] = h;
    } else if (tid < 256) {
        int e = tid - 128;
        float p = 0.f;
#pragma unroll 8
        for (int k = 0; k < 256; k++) p += W_ph[k] * W_upd[k * 128 + e];
        sm.phq[e] = p;
    }
    __syncthreads();
    if (tid < 128) sm.q[tid] = sm.hhat[tid] + sm.phq[tid];   // t=0 placeholder q
    __syncthreads();

    unsigned wm = 0u;        // per-warp mask bits: bit i <-> s = warp*32+i
    int first_r = 0;
    double logp_sum = 0.0;   // tid 0

    for (int t = 0; t < SS; t++) {
        // ---- P1: compat (gK; bitmask-skip) + per-warp per-head max ----
        {
            float4 qv = *(float4*)&sm.q[lane * 4];
            int h = lane >> 2;
            float mx = NEGINF;
#pragma unroll 8
            for (int i = 0; i < 32; i++) {
                int s = warp * 32 + i;
                if ((wm >> i) & 1u) {
                    if ((lane & 3) == 0) sm.compat[h * 1032 + s] = NEGINF;
                } else {
                    float4 g = *(const float4*)(projb + (size_t)s * PC + lane * 4);
                    float v = g.x*qv.x + g.y*qv.y + g.z*qv.z + g.w*qv.w;
                    v += __shfl_xor_sync(FULLM, v, 1);
                    v += __shfl_xor_sync(FULLM, v, 2);
                    float cv = v * 0.25f;
                    mx = fmaxf(mx, cv);
                    if ((lane & 3) == 0) sm.compat[h * 1032 + s] = cv;
                }
            }
            if ((lane & 3) == 0) sm.redv8[warp * 8 + h] = mx;
        }
        __syncthreads();

        // ---- P3: hm (order-free max over 32 warps) + exp chain + warp sum ----
        {
            int gh = tid >> 7, j = tid & 127;
            float hm = sm.redv8[gh];
#pragma unroll
            for (int w2 = 1; w2 < 32; w2++)
                hm = fmaxf(hm, sm.redv8[w2 * 8 + gh]);
            float se = 0.f;
#pragma unroll
            for (int ii = 0; ii < 8; ii++) {
                int idx = gh * 1032 + j + ii * 128;
                float ev = __nv_expf(sm.compat[idx] - hm);
                sm.compat[idx] = ev;
                se += ev;
            }
#pragma unroll
            for (int off = 16; off; off >>= 1)
                se += __shfl_xor_sync(FULLM, se, off);
            if (lane == 0) sm.redv2[warp] = se;
        }
        __syncthreads();

        // ---- P4: invs replay + heads partials (gV; bitmask-skip) ----
        {
            int h = lane >> 2;
            float s4 = sm.redv2[h*4] + sm.redv2[h*4+1] + sm.redv2[h*4+2] + sm.redv2[h*4+3];
            float invs = 1.0f / s4;
            float4 acc = make_float4(0.f, 0.f, 0.f, 0.f);
#pragma unroll 8
            for (int i = 0; i < 32; i++) {
                int s = warp * 32 + i;
                if (!((wm >> i) & 1u)) {
                    float a = sm.compat[h * 1032 + s] * invs;
                    float4 g = *(const float4*)(projb + (size_t)s * PC + 128 + lane * 4);
                    acc.x += a*g.x; acc.y += a*g.y; acc.z += a*g.z; acc.w += a*g.w;
                }
            }
            ((float4*)&sm.part[warp * 128])[lane] = acc;
        }
        __syncthreads();

        // ---- P5: heads reduce (replay of original 2-stage order) ----
        if (tid < 128) {
            float hsum = 0.f;
#pragma unroll
            for (int g = 0; g < 8; g++) {
                float pg = sm.part[(g*4+0)*128+tid] + sm.part[(g*4+1)*128+tid]
                         + sm.part[(g*4+2)*128+tid] + sm.part[(g*4+3)*128+tid];
                hsum += pg;
            }
            sm.heads[tid] = hsum;
        }
        __syncthreads();

        // ---- P6: glimpse ----
        if (tid < 128) {
            float gl = 0.f;
#pragma unroll 8
            for (int f = 0; f < 128; f++) gl += sm.heads[f] * sm.wout[f*128+tid];
            sm.glim[tid] = gl;
        }
        __syncthreads();

        // ---- P7: raw logit dots (logitK; bitmask-skip), then parallel tanh ----
        {
            float4 hv = *(float4*)&sm.glim[lane * 4];
#pragma unroll 8
            for (int i = 0; i < 32; i++) {
                int s = warp * 32 + i;
                if (!((wm >> i) & 1u)) {
                    float4 g = *(const float4*)(projb + (size_t)s * PC + 256 + lane * 4);
                    float v = g.x*hv.x + g.y*hv.y + g.z*hv.z + g.w*hv.w;
#pragma unroll
                    for (int off = 16; off; off >>= 1)
                        v += __shfl_xor_sync(FULLM, v, off);
                    if (lane == 0) sm.logits[s] = v;   // raw dot staged
                }
            }
            __syncwarp();
            // one tanh per lane: lane i finalizes s = warp*32 + i
            {
                int s = warp * 32 + lane;
                float raw = sm.logits[s];              // stale if masked (discarded)
                float lv = ((wm >> lane) & 1u) ? NEGINF
                         : __fmul_rn(10.0f, xla_tanh(__fmul_rn(raw, INV_SQRT_E)));
                sm.logits[s] = lv;
                float v = lv;                          // per-warp max (order-free)
#pragma unroll
                for (int off = 16; off; off >>= 1)
                    v = fmaxf(v, __shfl_xor_sync(FULLM, v, off));
                if (lane == 0) sm.redv[warp] = v;
            }
        }
        __syncthreads();

        // ---- P8: m replay; pair-exp + warp shfl-down tree -> redv2[w<16] ----
        float m_r;
        {
            m_r = sm.redv[0];
#pragma unroll
            for (int w2 = 1; w2 < 32; w2++) m_r = fmaxf(m_r, sm.redv[w2]);
            if (tid < 512) {
                float e0 = __nv_expf(__fsub_rn(sm.logits[2*tid],     m_r));
                float e1 = __nv_expf(__fsub_rn(sm.logits[2*tid + 1], m_r));
                float v = __fadd_rn(e0, e1);
                v = __fadd_rn(v, __shfl_down_sync(FULLM, v, 16));
                v = __fadd_rn(v, __shfl_down_sync(FULLM, v, 8));
                v = __fadd_rn(v, __shfl_down_sync(FULLM, v, 4));
                v = __fadd_rn(v, __shfl_down_sync(FULLM, v, 2));
                v = __fadd_rn(v, __shfl_down_sync(FULLM, v, 1));
                if (lane == 0) sm.redv2[warp] = v;
            }
        }
        __syncthreads();

        // ---- P9: L replay (exact tree), lp, per-warp argmax ----
        float L_r;
        {
            float a[16];
#pragma unroll
            for (int i2 = 0; i2 < 16; i2++) a[i2] = sm.redv2[i2];
#pragma unroll
            for (int off = 8; off; off >>= 1)
#pragma unroll
                for (int i2 = 0; i2 < 8; i2++)
                    if (i2 < off) a[i2] = __fadd_rn(a[i2], a[i2 + off]);
            L_r = __nv_logf(a[0]);

            float lp = __fsub_rn(__fsub_rn(sm.logits[tid], m_r), L_r);
            float v = lp;
            int idx = tid;
#pragma unroll
            for (int off = 16; off; off >>= 1) {
                float ov = __shfl_xor_sync(FULLM, v, off);
                int   oi = __shfl_xor_sync(FULLM, idx, off);
                if (ov > v || (ov == v && oi < idx)) { v = ov; idx = oi; }
            }
            if (lane == 0) { sm.redv3[warp] = v; sm.redi[warp] = idx; }
        }
        __syncthreads();

        // ---- P10: city replay; bitmask/state update; q for next step ----
        {
            float bv = sm.redv3[0]; int bi = sm.redi[0];
#pragma unroll
            for (int w2 = 1; w2 < 32; w2++) {
                float ov = sm.redv3[w2]; int oi = sm.redi[w2];
                if (ov > bv || (ov == bv && oi < bi)) { bv = ov; bi = oi; }
            }
            int city = bi;
            if (t == 0) first_r = city;
            if ((city >> 5) == warp) wm |= 1u << (city & 31);
            if (tid == 0) {
                logp_sum += (double)__fsub_rn(__fsub_rn(sm.logits[city], m_r), L_r);
                out[BB + b * SS + t] = (float)city;
            }
            if (tid < 128) {
                float pf = projb[(size_t)first_r * PC + 384 + tid];
                float pl = projb[(size_t)city   * PC + 512 + tid];
                sm.q[tid] = sm.hhat[tid] + (pf + pl);
            }
        }
        __syncthreads();
    }

    if (tid == 0) out[b] = (float)logp_sum;
}

// ============================================================================
extern "C" void kernel_launch(void* const* d_in, const int* in_sizes, int n_in,
                              void* d_out, int out_size) {
    const float* enc    = (const float*)d_in[0];
    const float* W_ctx  = (const float*)d_in[1];
    const float* W_upd  = (const float*)d_in[2];
    const float* W_node = (const float*)d_in[3];
    const float* W_out  = (const float*)d_in[4];
    const float* W_ph   = (const float*)d_in[5];
    float* out = (float*)d_out;

    static const int GEMM_SMEM = (128 * 65 + 128 * 128) * sizeof(float);
    static const int DEC_SMEM  = (int)sizeof(DS);
    cudaFuncSetAttribute(gemm_kernel,   cudaFuncAttributeMaxDynamicSharedMemorySize, GEMM_SMEM);
    cudaFuncSetAttribute(decode_kernel, cudaFuncAttributeMaxDynamicSharedMemorySize, DEC_SMEM);

    prep_kernel<<<16, 1024>>>(W_node, W_upd);
    gemm_kernel<<<dim3((BB * SS) / 64, PC / 128), 256, GEMM_SMEM>>>(enc);
    decode_kernel<<<BB, 1024, DEC_SMEM>>>(enc, W_ctx, W_upd, W_out, W_ph, out);
}

// round 11
// speedup vs baseline: 1.6810x; 1.0255x over previous
#include <cuda_runtime.h>
#include <math.h>
#include <stdint.h>

#define BB 64
#define SS 1024
#define EE 128
#define PC 640              // gK(128) gV(128) logitK(128) P1(128) P2(128)
#define INV_SQRT_E  0.08838834764831845f
#define FULLM 0xffffffffu

extern "C" __device__ float __nv_expf(float);
extern "C" __device__ float __nv_logf(float);

// XLA f32 tanh (frozen numerics — do not touch)
__device__ __forceinline__ float xla_tanh(float x) {
    float xc = fminf(fmaxf(x, -7.99881172180175781f), 7.99881172180175781f);
    float x2 = __fmul_rn(xc, xc);
    float p = __fadd_rn(__fmul_rn(x2, -2.76076847742355e-16f), 2.00018790482477e-13f);
    p = __fadd_rn(__fmul_rn(x2, p), -8.60467152213735e-11f);
    p = __fadd_rn(__fmul_rn(x2, p), 5.12229709037114e-08f);
    p = __fadd_rn(__fmul_rn(x2, p), 1.48572235717979e-05f);
    p = __fadd_rn(__fmul_rn(x2, p), 6.37261928875436e-04f);
    p = __fadd_rn(__fmul_rn(x2, p), 4.89352455891786e-03f);
    p = __fmul_rn(xc, p);
    float q = __fadd_rn(__fmul_rn(x2, 1.19825839466702e-06f), 1.18534705686654e-04f);
    q = __fadd_rn(__fmul_rn(x2, q), 2.26843463243900e-03f);
    q = __fadd_rn(__fmul_rn(x2, q), 4.89352518554385e-03f);
    float r = __fdiv_rn(p, q);
    return (fabsf(x) < 0.0004f) ? x : r;
}

__device__ float g_Wall[128 * PC];
__device__ float g_proj[(size_t)BB * SS * PC];   // 168 MB

// ============================================================================
__global__ void prep_kernel(const float* __restrict__ W_node,
                            const float* __restrict__ W_upd) {
    int tid = blockIdx.x * blockDim.x + threadIdx.x;
    int stride = blockDim.x * gridDim.x;
    for (int idx = tid; idx < 128 * 384; idx += stride) {
        int k = idx / 384, c = idx % 384;
        g_Wall[k * PC + c] = W_node[k * 384 + c];
    }
    for (int idx = tid; idx < 256 * 128; idx += stride) {
        int k2 = idx >> 7, j = idx & 127;
        float v = W_upd[idx];
        if (k2 < 128) g_Wall[k2 * PC + 384 + j] = v;
        else          g_Wall[(k2 - 128) * PC + 512 + j] = v;
    }
}

// ============================================================================
__global__ __launch_bounds__(256) void gemm_kernel(const float* __restrict__ A) {
    extern __shared__ float sh[];
    float* As = sh;              // [128][65]
    float* Bs = sh + 128 * 65;   // [128][128]
    int row0 = blockIdx.x * 64, col0 = blockIdx.y * 128, tid = threadIdx.x;

    for (int idx = tid; idx < 64 * 128; idx += 256) {
        int r = idx >> 7, k = idx & 127;
        As[k * 65 + r] = A[(size_t)(row0 + r) * 128 + k];
    }
    for (int idx = tid; idx < 128 * 128; idx += 256) {
        int k = idx >> 7, c = idx & 127;
        Bs[k * 128 + c] = g_Wall[k * PC + col0 + c];
    }
    __syncthreads();

    int tx = tid & 15, ty = tid >> 4;
    int r0 = ty * 4, c0 = tx * 8;
    float acc[4][8];
#pragma unroll
    for (int i = 0; i < 4; i++)
#pragma unroll
        for (int j = 0; j < 8; j++) acc[i][j] = 0.f;
#pragma unroll 8
    for (int k = 0; k < 128; k++) {
        float a0 = As[k*65+r0], a1 = As[k*65+r0+1], a2 = As[k*65+r0+2], a3 = As[k*65+r0+3];
        float4 b0 = *(float4*)&Bs[k*128+c0];
        float4 b1 = *(float4*)&Bs[k*128+c0+4];
        float bb[8] = {b0.x,b0.y,b0.z,b0.w,b1.x,b1.y,b1.z,b1.w};
#pragma unroll
        for (int j = 0; j < 8; j++) {
            acc[0][j] += a0*bb[j]; acc[1][j] += a1*bb[j];
            acc[2][j] += a2*bb[j]; acc[3][j] += a3*bb[j];
        }
    }
#pragma unroll
    for (int i = 0; i < 4; i++) {
        size_t o = (size_t)(row0+r0+i)*PC + col0 + c0;
        *(float4*)&g_proj[o]   = make_float4(acc[i][0],acc[i][1],acc[i][2],acc[i][3]);
        *(float4*)&g_proj[o+4] = make_float4(acc[i][4],acc[i][5],acc[i][6],acc[i][7]);
    }
}

// ============================================================================
// Decode: branch-free streaming loops (unconditional loads + selects, all
// bit-exact identities), tree-reduced order-free scans, register-cached pf.
// All value-producing arithmetic orders identical to R10.
// ============================================================================
struct DS {
    float wout[128 * 128];
    float compat[8 * 1032];
    float part[32 * 128];
    float logits[1024];
    float q[128], hhat[128], phq[128], heads[128], glim[128];
    float redv8[32 * 8];  // P1: per-warp per-head maxes
    float redv[32];       // P7: per-warp logit maxes
    float redv2[32];      // P3: per-warp exp sums | P8: 16 pair-tree partials
    float redv3[32];      // P9: per-warp argmax value
    int   redi[32];       // P9: per-warp argmax index
};

__global__ __launch_bounds__(1024, 1) void decode_kernel(
    const float* __restrict__ enc,
    const float* __restrict__ W_ctx,
    const float* __restrict__ W_upd,
    const float* __restrict__ W_out,
    const float* __restrict__ W_ph,
    float* __restrict__ out)
{
    extern __shared__ char smem_raw[];
    DS& sm = *reinterpret_cast<DS*>(smem_raw);

    const int b = blockIdx.x, tid = threadIdx.x;
    const int lane = tid & 31, warp = tid >> 5;
    const float NEGINF = -INFINITY;

    const float* __restrict__ projb = g_proj + (size_t)b * SS * PC;
    const float* __restrict__ encb  = enc + (size_t)b * SS * EE;

    // ---- init (numerics identical to R10) ----
    for (int idx = tid; idx < 128 * 128; idx += 1024)
        sm.wout[idx] = W_out[idx];
    {
        int e = tid & 127, g = tid >> 7;
        float acc = 0.f;
        for (int i = 0; i < 128; i++)
            acc += encb[(size_t)(g * 128 + i) * EE + e];
        sm.part[g * 128 + e] = acc;
    }
    __syncthreads();
    if (tid < 128) {
        float m = 0.f;
#pragma unroll
        for (int g = 0; g < 8; g++) m += sm.part[g * 128 + tid];
        sm.q[tid] = m * (1.0f / 1024.0f);
    }
    __syncthreads();
    if (tid < 128) {
        float h = 0.f;
#pragma unroll 8
        for (int k = 0; k < 128; k++) h += sm.q[k] * W_ctx[k * 128 + tid];
        sm.hhat[tid] = h;
    } else if (tid < 256) {
        int e = tid - 128;
        float p = 0.f;
#pragma unroll 8
        for (int k = 0; k < 256; k++) p += W_ph[k] * W_upd[k * 128 + e];
        sm.phq[e] = p;
    }
    __syncthreads();
    if (tid < 128) sm.q[tid] = sm.hhat[tid] + sm.phq[tid];   // t=0 placeholder q
    __syncthreads();

    unsigned wm = 0u;        // per-warp mask bits: bit i <-> s = warp*32+i
    int first_r = 0;
    float pf_r = 0.f;        // register cache of projb[first*PC+384+tid] (tid<128)
    double logp_sum = 0.0;   // tid 0

    for (int t = 0; t < SS; t++) {
        // ---- P1: compat (unconditional gK loads, select) + per-head max ----
        {
            float4 qv = *(float4*)&sm.q[lane * 4];
            int h = lane >> 2;
            float mx = NEGINF;
#pragma unroll 8
            for (int i = 0; i < 32; i++) {
                int s = warp * 32 + i;
                float4 g = *(const float4*)(projb + (size_t)s * PC + lane * 4);
                float v = g.x*qv.x + g.y*qv.y + g.z*qv.z + g.w*qv.w;
                v += __shfl_xor_sync(FULLM, v, 1);
                v += __shfl_xor_sync(FULLM, v, 2);
                float cv = ((wm >> i) & 1u) ? NEGINF : v * 0.25f;
                mx = fmaxf(mx, cv);               // fmax(-inf) identity
                if ((lane & 3) == 0) sm.compat[h * 1032 + s] = cv;
            }
            if ((lane & 3) == 0) sm.redv8[warp * 8 + h] = mx;
        }
        __syncthreads();

        // ---- P3: hm (order-free fmax TREE over 32 warps) + exp chain + warp sum ----
        {
            int gh = tid >> 7, j = tid & 127;
            float a[32];
#pragma unroll
            for (int w2 = 0; w2 < 32; w2++) a[w2] = sm.redv8[w2 * 8 + gh];
#pragma unroll
            for (int off = 16; off; off >>= 1)
#pragma unroll
                for (int i2 = 0; i2 < 16; i2++)
                    if (i2 < off) a[i2] = fmaxf(a[i2], a[i2 + off]);
            float hm = a[0];
            float se = 0.f;
#pragma unroll
            for (int ii = 0; ii < 8; ii++) {
                int idx = gh * 1032 + j + ii * 128;
                float ev = __nv_expf(sm.compat[idx] - hm);
                sm.compat[idx] = ev;
                se += ev;                           // frozen serial chain
            }
#pragma unroll
            for (int off = 16; off; off >>= 1)
                se += __shfl_xor_sync(FULLM, se, off);
            if (lane == 0) sm.redv2[warp] = se;
        }
        __syncthreads();

        // ---- P4: invs replay + heads partials (unconditional; masked adds ±0) ----
        {
            int h = lane >> 2;
            float s4 = sm.redv2[h*4] + sm.redv2[h*4+1] + sm.redv2[h*4+2] + sm.redv2[h*4+3];
            float invs = 1.0f / s4;
            float4 acc = make_float4(0.f, 0.f, 0.f, 0.f);
#pragma unroll 8
            for (int i = 0; i < 32; i++) {
                int s = warp * 32 + i;
                float a = sm.compat[h * 1032 + s] * invs;   // masked: +0
                float4 g = *(const float4*)(projb + (size_t)s * PC + 128 + lane * 4);
                acc.x += a*g.x; acc.y += a*g.y; acc.z += a*g.z; acc.w += a*g.w;
            }
            ((float4*)&sm.part[warp * 128])[lane] = acc;
        }
        __syncthreads();

        // ---- P5: heads reduce (replay of original 2-stage order) ----
        if (tid < 128) {
            float hsum = 0.f;
#pragma unroll
            for (int g = 0; g < 8; g++) {
                float pg = sm.part[(g*4+0)*128+tid] + sm.part[(g*4+1)*128+tid]
                         + sm.part[(g*4+2)*128+tid] + sm.part[(g*4+3)*128+tid];
                hsum += pg;
            }
            sm.heads[tid] = hsum;
        }
        __syncthreads();

        // ---- P6: glimpse (frozen 128-deep chain) ----
        if (tid < 128) {
            float gl = 0.f;
#pragma unroll 8
            for (int f = 0; f < 128; f++) gl += sm.heads[f] * sm.wout[f*128+tid];
            sm.glim[tid] = gl;
        }
        __syncthreads();

        // ---- P7: raw logit dots (unconditional), parallel tanh + select ----
        {
            float4 hv = *(float4*)&sm.glim[lane * 4];
#pragma unroll 8
            for (int i = 0; i < 32; i++) {
                int s = warp * 32 + i;
                float4 g = *(const float4*)(projb + (size_t)s * PC + 256 + lane * 4);
                float v = g.x*hv.x + g.y*hv.y + g.z*hv.z + g.w*hv.w;
#pragma unroll
                for (int off = 16; off; off >>= 1)
                    v += __shfl_xor_sync(FULLM, v, off);
                if (lane == 0) sm.logits[s] = v;   // raw dot staged (all s)
            }
            __syncwarp();
            {
                int s = warp * 32 + lane;
                float raw = sm.logits[s];
                float lv = ((wm >> lane) & 1u) ? NEGINF
                         : __fmul_rn(10.0f, xla_tanh(__fmul_rn(raw, INV_SQRT_E)));
                sm.logits[s] = lv;
                float v = lv;
#pragma unroll
                for (int off = 16; off; off >>= 1)
                    v = fmaxf(v, __shfl_xor_sync(FULLM, v, off));
                if (lane == 0) sm.redv[warp] = v;
            }
        }
        __syncthreads();

        // ---- P8: m (order-free fmax TREE); pair-exp + warp shfl-down tree ----
        float m_r;
        {
            float a[32];
#pragma unroll
            for (int w2 = 0; w2 < 32; w2++) a[w2] = sm.redv[w2];
#pragma unroll
            for (int off = 16; off; off >>= 1)
#pragma unroll
                for (int i2 = 0; i2 < 16; i2++)
                    if (i2 < off) a[i2] = fmaxf(a[i2], a[i2 + off]);
            m_r = a[0];
            if (tid < 512) {
                float e0 = __nv_expf(__fsub_rn(sm.logits[2*tid],     m_r));
                float e1 = __nv_expf(__fsub_rn(sm.logits[2*tid + 1], m_r));
                float v = __fadd_rn(e0, e1);
                v = __fadd_rn(v, __shfl_down_sync(FULLM, v, 16));
                v = __fadd_rn(v, __shfl_down_sync(FULLM, v, 8));
                v = __fadd_rn(v, __shfl_down_sync(FULLM, v, 4));
                v = __fadd_rn(v, __shfl_down_sync(FULLM, v, 2));
                v = __fadd_rn(v, __shfl_down_sync(FULLM, v, 1));
                if (lane == 0) sm.redv2[warp] = v;
            }
        }
        __syncthreads();

        // ---- P9: L replay (exact tree), lp, per-warp argmax ----
        float L_r;
        {
            float a[16];
#pragma unroll
            for (int i2 = 0; i2 < 16; i2++) a[i2] = sm.redv2[i2];
#pragma unroll
            for (int off = 8; off; off >>= 1)
#pragma unroll
                for (int i2 = 0; i2 < 8; i2++)
                    if (i2 < off) a[i2] = __fadd_rn(a[i2], a[i2 + off]);
            L_r = __nv_logf(a[0]);

            float lp = __fsub_rn(__fsub_rn(sm.logits[tid], m_r), L_r);
            float v = lp;
            int idx = tid;
#pragma unroll
            for (int off = 16; off; off >>= 1) {
                float ov = __shfl_xor_sync(FULLM, v, off);
                int   oi = __shfl_xor_sync(FULLM, idx, off);
                if (ov > v || (ov == v && oi < idx)) { v = ov; idx = oi; }
            }
            if (lane == 0) { sm.redv3[warp] = v; sm.redi[warp] = idx; }
        }
        __syncthreads();

        // ---- P10: city (lexicographic-max TREE, order-free); state; next q ----
        {
            float av[32]; int ai[32];
#pragma unroll
            for (int w2 = 0; w2 < 32; w2++) { av[w2] = sm.redv3[w2]; ai[w2] = sm.redi[w2]; }
#pragma unroll
            for (int off = 16; off; off >>= 1)
#pragma unroll
                for (int i2 = 0; i2 < 16; i2++)
                    if (i2 < off) {
                        float ov = av[i2 + off]; int oi = ai[i2 + off];
                        if (ov > av[i2] || (ov == av[i2] && oi < ai[i2])) { av[i2] = ov; ai[i2] = oi; }
                    }
            int city = ai[0];
            if (t == 0) {
                first_r = city;
                if (tid < 128) pf_r = projb[(size_t)first_r * PC + 384 + tid];
            }
            if ((city >> 5) == warp) wm |= 1u << (city & 31);
            if (tid == 0) {
                logp_sum += (double)__fsub_rn(__fsub_rn(sm.logits[city], m_r), L_r);
                out[BB + b * SS + t] = (float)city;
            }
            if (tid < 128) {
                float pl = projb[(size_t)city * PC + 512 + tid];
                sm.q[tid] = sm.hhat[tid] + (pf_r + pl);   // same association as ref
            }
        }
        __syncthreads();
    }

    if (tid == 0) out[b] = (float)logp_sum;
}

// ============================================================================
extern "C" void kernel_launch(void* const* d_in, const int* in_sizes, int n_in,
                              void* d_out, int out_size) {
    const float* enc    = (const float*)d_in[0];
    const float* W_ctx  = (const float*)d_in[1];
    const float* W_upd  = (const float*)d_in[2];
    const float* W_node = (const float*)d_in[3];
    const float* W_out  = (const float*)d_in[4];
    const float* W_ph   = (const float*)d_in[5];
    float* out = (float*)d_out;

    static const int GEMM_SMEM = (128 * 65 + 128 * 128) * sizeof(float);
    static const int DEC_SMEM  = (int)sizeof(DS);
    cudaFuncSetAttribute(gemm_kernel,   cudaFuncAttributeMaxDynamicSharedMemorySize, GEMM_SMEM);
    cudaFuncSetAttribute(decode_kernel, cudaFuncAttributeMaxDynamicSharedMemorySize, DEC_SMEM);

    prep_kernel<<<16, 1024>>>(W_node, W_upd);
    gemm_kernel<<<dim3((BB * SS) / 64, PC / 128), 256, GEMM_SMEM>>>(enc);
    decode_kernel<<<BB, 1024, DEC_SMEM>>>(enc, W_ctx, W_upd, W_out, W_ph, out);
}

// round 12
// speedup vs baseline: 1.7470x; 1.0392x over previous
#include <cuda_runtime.h>
#include <math.h>
#include <stdint.h>

#define BB 64
#define SS 1024
#define EE 128
#define PC 640              // gK(128) gV(128) logitK(128) P1(128) P2(128)
#define INV_SQRT_E  0.08838834764831845f
#define FULLM 0xffffffffu

extern "C" __device__ float __nv_expf(float);
extern "C" __device__ float __nv_logf(float);

// XLA f32 tanh (frozen numerics — do not touch)
__device__ __forceinline__ float xla_tanh(float x) {
    float xc = fminf(fmaxf(x, -7.99881172180175781f), 7.99881172180175781f);
    float x2 = __fmul_rn(xc, xc);
    float p = __fadd_rn(__fmul_rn(x2, -2.76076847742355e-16f), 2.00018790482477e-13f);
    p = __fadd_rn(__fmul_rn(x2, p), -8.60467152213735e-11f);
    p = __fadd_rn(__fmul_rn(x2, p), 5.12229709037114e-08f);
    p = __fadd_rn(__fmul_rn(x2, p), 1.48572235717979e-05f);
    p = __fadd_rn(__fmul_rn(x2, p), 6.37261928875436e-04f);
    p = __fadd_rn(__fmul_rn(x2, p), 4.89352455891786e-03f);
    p = __fmul_rn(xc, p);
    float q = __fadd_rn(__fmul_rn(x2, 1.19825839466702e-06f), 1.18534705686654e-04f);
    q = __fadd_rn(__fmul_rn(x2, q), 2.26843463243900e-03f);
    q = __fadd_rn(__fmul_rn(x2, q), 4.89352518554385e-03f);
    float r = __fdiv_rn(p, q);
    return (fabsf(x) < 0.0004f) ? x : r;
}

// order-free fmax over a float4 (fmax assoc+comm -> any shape bit-identical)
__device__ __forceinline__ float fmax4(float4 v) {
    return fmaxf(fmaxf(v.x, v.y), fmaxf(v.z, v.w));
}

__device__ float g_Wall[128 * PC];
__device__ float g_proj[(size_t)BB * SS * PC];   // 168 MB

// ============================================================================
__global__ void prep_kernel(const float* __restrict__ W_node,
                            const float* __restrict__ W_upd) {
    int tid = blockIdx.x * blockDim.x + threadIdx.x;
    int stride = blockDim.x * gridDim.x;
    for (int idx = tid; idx < 128 * 384; idx += stride) {
        int k = idx / 384, c = idx % 384;
        g_Wall[k * PC + c] = W_node[k * 384 + c];
    }
    for (int idx = tid; idx < 256 * 128; idx += stride) {
        int k2 = idx >> 7, j = idx & 127;
        float v = W_upd[idx];
        if (k2 < 128) g_Wall[k2 * PC + 384 + j] = v;
        else          g_Wall[(k2 - 128) * PC + 512 + j] = v;
    }
}

// ============================================================================
__global__ __launch_bounds__(256) void gemm_kernel(const float* __restrict__ A) {
    extern __shared__ float sh[];
    float* As = sh;              // [128][65]
    float* Bs = sh + 128 * 65;   // [128][128]
    int row0 = blockIdx.x * 64, col0 = blockIdx.y * 128, tid = threadIdx.x;

    for (int idx = tid; idx < 64 * 128; idx += 256) {
        int r = idx >> 7, k = idx & 127;
        As[k * 65 + r] = A[(size_t)(row0 + r) * 128 + k];
    }
    for (int idx = tid; idx < 128 * 128; idx += 256) {
        int k = idx >> 7, c = idx & 127;
        Bs[k * 128 + c] = g_Wall[k * PC + col0 + c];
    }
    __syncthreads();

    int tx = tid & 15, ty = tid >> 4;
    int r0 = ty * 4, c0 = tx * 8;
    float acc[4][8];
#pragma unroll
    for (int i = 0; i < 4; i++)
#pragma unroll
        for (int j = 0; j < 8; j++) acc[i][j] = 0.f;
#pragma unroll 8
    for (int k = 0; k < 128; k++) {
        float a0 = As[k*65+r0], a1 = As[k*65+r0+1], a2 = As[k*65+r0+2], a3 = As[k*65+r0+3];
        float4 b0 = *(float4*)&Bs[k*128+c0];
        float4 b1 = *(float4*)&Bs[k*128+c0+4];
        float bb[8] = {b0.x,b0.y,b0.z,b0.w,b1.x,b1.y,b1.z,b1.w};
#pragma unroll
        for (int j = 0; j < 8; j++) {
            acc[0][j] += a0*bb[j]; acc[1][j] += a1*bb[j];
            acc[2][j] += a2*bb[j]; acc[3][j] += a3*bb[j];
        }
    }
#pragma unroll
    for (int i = 0; i < 4; i++) {
        size_t o = (size_t)(row0+r0+i)*PC + col0 + c0;
        *(float4*)&g_proj[o]   = make_float4(acc[i][0],acc[i][1],acc[i][2],acc[i][3]);
        *(float4*)&g_proj[o+4] = make_float4(acc[i][4],acc[i][5],acc[i][6],acc[i][7]);
    }
}

// ============================================================================
// Decode. Spill-free reductions; 3-shfl logits butterfly; frozen numerics.
// ============================================================================
struct DS {
    float wout[128 * 128];
    float compat[8 * 1032];
    float part[32 * 128];
    float logits[1024];
    float q[128], hhat[128], phq[128], heads[128], glim[128];
    float redv8[8 * 32];  // [head][warp] per-warp per-head maxes
    float redv[32];       // P7: per-warp logit maxes
    float redv2[32];      // P3: per-warp exp sums | P8: 16 pair-tree partials
    float redv3[32];      // P9: per-warp argmax value
    int   redi[32];       // P9: per-warp argmax index
};

__global__ __launch_bounds__(1024, 1) void decode_kernel(
    const float* __restrict__ enc,
    const float* __restrict__ W_ctx,
    const float* __restrict__ W_upd,
    const float* __restrict__ W_out,
    const float* __restrict__ W_ph,
    float* __restrict__ out)
{
    extern __shared__ char smem_raw[];
    DS& sm = *reinterpret_cast<DS*>(smem_raw);

    const int b = blockIdx.x, tid = threadIdx.x;
    const int lane = tid & 31, warp = tid >> 5;
    const float NEGINF = -INFINITY;

    const float* __restrict__ projb = g_proj + (size_t)b * SS * PC;
    const float* __restrict__ encb  = enc + (size_t)b * SS * EE;

    // ---- init (numerics identical to R11) ----
    for (int idx = tid; idx < 128 * 128; idx += 1024)
        sm.wout[idx] = W_out[idx];
    {
        int e = tid & 127, g = tid >> 7;
        float acc = 0.f;
        for (int i = 0; i < 128; i++)
            acc += encb[(size_t)(g * 128 + i) * EE + e];
        sm.part[g * 128 + e] = acc;
    }
    __syncthreads();
    if (tid < 128) {
        float m = 0.f;
#pragma unroll
        for (int g = 0; g < 8; g++) m += sm.part[g * 128 + tid];
        sm.q[tid] = m * (1.0f / 1024.0f);
    }
    __syncthreads();
    if (tid < 128) {
        float h = 0.f;
#pragma unroll 8
        for (int k = 0; k < 128; k++) h += sm.q[k] * W_ctx[k * 128 + tid];
        sm.hhat[tid] = h;
    } else if (tid < 256) {
        int e = tid - 128;
        float p = 0.f;
#pragma unroll 8
        for (int k = 0; k < 256; k++) p += W_ph[k] * W_upd[k * 128 + e];
        sm.phq[e] = p;
    }
    __syncthreads();
    if (tid < 128) sm.q[tid] = sm.hhat[tid] + sm.phq[tid];
    __syncthreads();

    unsigned wm = 0u;
    int first_r = 0;
    float pf_r = 0.f;
    double logp_sum = 0.0;

    for (int t = 0; t < SS; t++) {
        // ---- P1: compat (unconditional gK loads, select) + per-head max ----
        {
            float4 qv = *(float4*)&sm.q[lane * 4];
            int h = lane >> 2;
            float mx = NEGINF;
#pragma unroll 8
            for (int i = 0; i < 32; i++) {
                int s = warp * 32 + i;
                float4 g = *(const float4*)(projb + (size_t)s * PC + lane * 4);
                float v = g.x*qv.x + g.y*qv.y + g.z*qv.z + g.w*qv.w;
                v += __shfl_xor_sync(FULLM, v, 1);
                v += __shfl_xor_sync(FULLM, v, 2);
                float cv = ((wm >> i) & 1u) ? NEGINF : v * 0.25f;
                mx = fmaxf(mx, cv);
                if ((lane & 3) == 0) sm.compat[h * 1032 + s] = cv;
            }
            if ((lane & 3) == 0) sm.redv8[h * 32 + warp] = mx;
        }
        __syncthreads();

        // ---- P3: hm (order-free fmax, vectorized) + frozen exp chain + warp sum ----
        {
            int gh = tid >> 7, j = tid & 127;
            const float4* r8 = (const float4*)&sm.redv8[gh * 32];
            float hm = fmaxf(fmaxf(fmax4(r8[0]), fmax4(r8[1])),
                             fmaxf(fmax4(r8[2]), fmax4(r8[3])));
            hm = fmaxf(hm, fmaxf(fmaxf(fmax4(r8[4]), fmax4(r8[5])),
                                 fmaxf(fmax4(r8[6]), fmax4(r8[7]))));
            float se = 0.f;
#pragma unroll
            for (int ii = 0; ii < 8; ii++) {
                int idx = gh * 1032 + j + ii * 128;
                float ev = __nv_expf(sm.compat[idx] - hm);
                sm.compat[idx] = ev;
                se += ev;                         // frozen serial chain
            }
#pragma unroll
            for (int off = 16; off; off >>= 1)
                se += __shfl_xor_sync(FULLM, se, off);
            if (lane == 0) sm.redv2[warp] = se;
        }
        __syncthreads();

        // ---- P4: invs replay + heads partials (vectorized compat reads) ----
        {
            int h = lane >> 2;
            float s4 = sm.redv2[h*4] + sm.redv2[h*4+1] + sm.redv2[h*4+2] + sm.redv2[h*4+3];
            float invs = 1.0f / s4;
            float4 acc = make_float4(0.f, 0.f, 0.f, 0.f);
#pragma unroll
            for (int i4 = 0; i4 < 8; i4++) {
                float4 c4 = *(const float4*)&sm.compat[h * 1032 + warp * 32 + i4 * 4];
                float av[4] = {c4.x, c4.y, c4.z, c4.w};
#pragma unroll
                for (int k = 0; k < 4; k++) {
                    int s = warp * 32 + i4 * 4 + k;
                    float a = av[k] * invs;       // masked: +0 (identity add)
                    float4 g = *(const float4*)(projb + (size_t)s * PC + 128 + lane * 4);
                    acc.x += a*g.x; acc.y += a*g.y; acc.z += a*g.z; acc.w += a*g.w;
                }
            }
            ((float4*)&sm.part[warp * 128])[lane] = acc;
        }
        __syncthreads();

        // ---- P5: heads reduce (frozen 2-stage order) ----
        if (tid < 128) {
            float hsum = 0.f;
#pragma unroll
            for (int g = 0; g < 8; g++) {
                float pg = sm.part[(g*4+0)*128+tid] + sm.part[(g*4+1)*128+tid]
                         + sm.part[(g*4+2)*128+tid] + sm.part[(g*4+3)*128+tid];
                hsum += pg;
            }
            sm.heads[tid] = hsum;
        }
        __syncthreads();

        // ---- P6: glimpse (frozen chain) ----
        if (tid < 128) {
            float gl = 0.f;
#pragma unroll 8
            for (int f = 0; f < 128; f++) gl += sm.heads[f] * sm.wout[f*128+tid];
            sm.glim[tid] = gl;
        }
        __syncthreads();

        // ---- P7: logits via 3-shfl butterfly (reference tree node values) ----
        {
            int g = lane >> 3, j = lane & 7;
            // hoisted glim registers: float4s at indices j, j+8, j+16, j+24
            float4 h0 = *(float4*)&sm.glim[(j     ) * 4];
            float4 h1 = *(float4*)&sm.glim[(j +  8) * 4];
            float4 h2 = *(float4*)&sm.glim[(j + 16) * 4];
            float4 h3 = *(float4*)&sm.glim[(j + 24) * 4];
#pragma unroll
            for (int m = 0; m < 8; m++) {
                int s = warp * 32 + m * 4 + g;
                const float* row = projb + (size_t)s * PC + 256;
                float4 gA = *(const float4*)(row + (j     ) * 4);
                float4 gB = *(const float4*)(row + (j +  8) * 4);
                float4 gC = *(const float4*)(row + (j + 16) * 4);
                float4 gD = *(const float4*)(row + (j + 24) * 4);
                // d_k = mul/fma chain over 4 dims (same form as reference)
                float dA = gA.x*h0.x + gA.y*h0.y + gA.z*h0.z + gA.w*h0.w; // d_j
                float dB = gB.x*h1.x + gB.y*h1.y + gB.z*h1.z + gB.w*h1.w; // d_{j+8}
                float dC = gC.x*h2.x + gC.y*h2.y + gC.z*h2.z + gC.w*h2.w; // d_{j+16}
                float dD = gD.x*h3.x + gD.y*h3.y + gD.z*h3.z + gD.w*h3.w; // d_{j+24}
                float t16a = dA + dC;            // t16[j]
                float t16b = dB + dD;            // t16[j+8]
                float v = t16a + t16b;           // t8[j]
                v += __shfl_xor_sync(FULLM, v, 4);   // t4
                v += __shfl_xor_sync(FULLM, v, 2);   // t2
                v += __shfl_xor_sync(FULLM, v, 1);   // t1
                if (j == 0) sm.logits[s] = v;    // raw dot staged
            }
            __syncwarp();
            {
                int s = warp * 32 + lane;
                float raw = sm.logits[s];
                float lv = ((wm >> lane) & 1u) ? NEGINF
                         : __fmul_rn(10.0f, xla_tanh(__fmul_rn(raw, INV_SQRT_E)));
                sm.logits[s] = lv;
                float v = lv;                    // per-warp max (order-free)
#pragma unroll
                for (int off = 16; off; off >>= 1)
                    v = fmaxf(v, __shfl_xor_sync(FULLM, v, off));
                if (lane == 0) sm.redv[warp] = v;
            }
        }
        __syncthreads();

        // ---- P8: m (order-free fmax, vectorized); frozen pair-exp tree ----
        float m_r;
        {
            const float4* rv = (const float4*)&sm.redv[0];
            m_r = fmaxf(fmaxf(fmax4(rv[0]), fmax4(rv[1])),
                        fmaxf(fmax4(rv[2]), fmax4(rv[3])));
            m_r = fmaxf(m_r, fmaxf(fmaxf(fmax4(rv[4]), fmax4(rv[5])),
                                   fmaxf(fmax4(rv[6]), fmax4(rv[7]))));
            if (tid < 512) {
                float e0 = __nv_expf(__fsub_rn(sm.logits[2*tid],     m_r));
                float e1 = __nv_expf(__fsub_rn(sm.logits[2*tid + 1], m_r));
                float v = __fadd_rn(e0, e1);
                v = __fadd_rn(v, __shfl_down_sync(FULLM, v, 16));
                v = __fadd_rn(v, __shfl_down_sync(FULLM, v, 8));
                v = __fadd_rn(v, __shfl_down_sync(FULLM, v, 4));
                v = __fadd_rn(v, __shfl_down_sync(FULLM, v, 2));
                v = __fadd_rn(v, __shfl_down_sync(FULLM, v, 1));
                if (lane == 0) sm.redv2[warp] = v;
            }
        }
        __syncthreads();

        // ---- P9: L replay (FROZEN 16-elem tree), lp, per-warp argmax ----
        float L_r;
        {
            float4 a0 = *(float4*)&sm.redv2[0];
            float4 a1 = *(float4*)&sm.redv2[4];
            float4 a2 = *(float4*)&sm.redv2[8];
            float4 a3 = *(float4*)&sm.redv2[12];
            // off=8
            a0.x = __fadd_rn(a0.x, a2.x); a0.y = __fadd_rn(a0.y, a2.y);
            a0.z = __fadd_rn(a0.z, a2.z); a0.w = __fadd_rn(a0.w, a2.w);
            a1.x = __fadd_rn(a1.x, a3.x); a1.y = __fadd_rn(a1.y, a3.y);
            a1.z = __fadd_rn(a1.z, a3.z); a1.w = __fadd_rn(a1.w, a3.w);
            // off=4
            a0.x = __fadd_rn(a0.x, a1.x); a0.y = __fadd_rn(a0.y, a1.y);
            a0.z = __fadd_rn(a0.z, a1.z); a0.w = __fadd_rn(a0.w, a1.w);
            // off=2
            a0.x = __fadd_rn(a0.x, a0.z); a0.y = __fadd_rn(a0.y, a0.w);
            // off=1
            L_r = __nv_logf(__fadd_rn(a0.x, a0.y));

            float lp = __fsub_rn(__fsub_rn(sm.logits[tid], m_r), L_r);
            float v = lp;
            int idx = tid;
#pragma unroll
            for (int off = 16; off; off >>= 1) {
                float ov = __shfl_xor_sync(FULLM, v, off);
                int   oi = __shfl_xor_sync(FULLM, idx, off);
                if (ov > v || (ov == v && oi < idx)) { v = ov; idx = oi; }
            }
            if (lane == 0) { sm.redv3[warp] = v; sm.redi[warp] = idx; }
        }
        __syncthreads();

        // ---- P10: city (serial lexmax, order-free); state; next q ----
        {
            float bv = sm.redv3[0]; int bi = sm.redi[0];
#pragma unroll
            for (int w2 = 1; w2 < 32; w2++) {
                float ov = sm.redv3[w2]; int oi = sm.redi[w2];
                if (ov > bv || (ov == bv && oi < bi)) { bv = ov; bi = oi; }
            }
            int city = bi;
            if (t == 0) {
                first_r = city;
                if (tid < 128) pf_r = projb[(size_t)first_r * PC + 384 + tid];
            }
            if ((city >> 5) == warp) wm |= 1u << (city & 31);
            if (tid == 0) {
                logp_sum += (double)__fsub_rn(__fsub_rn(sm.logits[city], m_r), L_r);
                out[BB + b * SS + t] = (float)city;
            }
            if (tid < 128) {
                float pl = projb[(size_t)city * PC + 512 + tid];
                sm.q[tid] = sm.hhat[tid] + (pf_r + pl);
            }
        }
        __syncthreads();
    }

    if (tid == 0) out[b] = (float)logp_sum;
}

// ============================================================================
extern "C" void kernel_launch(void* const* d_in, const int* in_sizes, int n_in,
                              void* d_out, int out_size) {
    const float* enc    = (const float*)d_in[0];
    const float* W_ctx  = (const float*)d_in[1];
    const float* W_upd  = (const float*)d_in[2];
    const float* W_node = (const float*)d_in[3];
    const float* W_out  = (const float*)d_in[4];
    const float* W_ph   = (const float*)d_in[5];
    float* out = (float*)d_out;

    static const int GEMM_SMEM = (128 * 65 + 128 * 128) * sizeof(float);
    static const int DEC_SMEM  = (int)sizeof(DS);
    cudaFuncSetAttribute(gemm_kernel,   cudaFuncAttributeMaxDynamicSharedMemorySize, GEMM_SMEM);
    cudaFuncSetAttribute(decode_kernel, cudaFuncAttributeMaxDynamicSharedMemorySize, DEC_SMEM);

    prep_kernel<<<16, 1024>>>(W_node, W_upd);
    gemm_kernel<<<dim3((BB * SS) / 64, PC / 128), 256, GEMM_SMEM>>>(enc);
    decode_kernel<<<BB, 1024, DEC_SMEM>>>(enc, W_ctx, W_upd, W_out, W_ph, out);
}